// round 3
// baseline (speedup 1.0000x reference)
#include <cuda_runtime.h>

// SSIM fused, (16,3,512,512) fp32, separable 11x11 Gaussian, VALID -> 502x502, mean.
// 4-field formulation: u=a+b, v=a-b; P=conv(u), M=conv(v), S=conv(u^2), D=conv(v^2)
// ssim = (P^2-M^2)(S-D-(P^2-M^2)) / ((P^2+M^2)(S+D-(P^2+M^2)))
// Packed f32x2 FMA; register-blocked separable passes; single kernel with
// last-block-done deterministic reduction.

#define WS      11
#define TILE_X  32
#define TILE_Y  40
#define IN_X    42          // TILE_X + 10
#define IN_Y    50          // TILE_Y + 10
#define IMG_W   512
#define OUT_W   502
#define NTX     16          // ceil(502/32)
#define NTY     13          // ceil(502/40)
#define NIMG    48
#define NBLOCKS (NIMG * NTX * NTY)

typedef unsigned long long u64;

__device__ double g_partials[NBLOCKS];
__device__ unsigned int g_count = 0;

__device__ __forceinline__ u64 pk2(float lo, float hi) {
    u64 r; asm("mov.b64 %0,{%1,%2};" : "=l"(r) : "f"(lo), "f"(hi)); return r;
}
__device__ __forceinline__ void upk2(float& lo, float& hi, u64 a) {
    asm("mov.b64 {%0,%1},%2;" : "=f"(lo), "=f"(hi) : "l"(a));
}
__device__ __forceinline__ u64 f2fma(u64 a, u64 b, u64 c) {
    u64 d; asm("fma.rn.f32x2 %0,%1,%2,%3;" : "=l"(d) : "l"(a), "l"(b), "l"(c)); return d;
}
__device__ __forceinline__ u64 f2mul(u64 a, u64 b) {
    u64 d; asm("mul.rn.f32x2 %0,%1,%2;" : "=l"(d) : "l"(a), "l"(b)); return d;
}

__global__ __launch_bounds__(256, 2)
void ssim_kernel(const float* __restrict__ img1,
                 const float* __restrict__ img2,
                 const float* __restrict__ win,
                 float* __restrict__ out)
{
    __shared__ u64 s_uv[IN_Y][IN_X + 1];   // packed (u,v): 50*43*8 = 17.2 KB
    __shared__ u64 s_pm[IN_Y][TILE_X + 1]; // packed (P,M) horizontal sums: 13.2 KB
    __shared__ u64 s_sd[IN_Y][TILE_X + 1]; // packed (S,D) horizontal sums: 13.2 KB
    __shared__ double s_red[8];

    const int tid = threadIdx.x;
    const int z   = blockIdx.z;
    const int c   = z % 3;
    const int ox  = blockIdx.x * TILE_X;
    const int oy  = blockIdx.y * TILE_Y;

    // 1D separable factors from the outer-product window.
    const float* w = win + c * WS * WS;
    const float inv_mid = 1.0f / w[5 * WS + 5];
    u64   ggr[WS];
    float gcf[WS];
    #pragma unroll
    for (int j = 0; j < WS; j++) {
        const float gr = w[5 * WS + j];
        ggr[j] = pk2(gr, gr);
        gcf[j] = w[j * WS + 5] * inv_mid;
    }

    const float* b1 = img1 + (size_t)z * IMG_W * IMG_W;
    const float* b2 = img2 + (size_t)z * IMG_W * IMG_W;

    // ---- Phase 0: load halo tile, pack (u, v) = (a+b, a-b) ----
    #pragma unroll
    for (int it = 0; it < 9; it++) {
        const int idx = tid + it * 256;
        if (idx < IN_Y * IN_X) {
            const int r  = idx / IN_X;
            const int cc = idx - r * IN_X;
            const int gy = oy + r;
            const int gx = ox + cc;
            float a = 0.0f, b = 0.0f;
            if (gy < IMG_W && gx < IMG_W) {
                a = b1[gy * IMG_W + gx];
                b = b2[gy * IMG_W + gx];
            }
            s_uv[r][cc] = pk2(a + b, a - b);
        }
    }
    __syncthreads();

    // ---- Phase 1: horizontal pass, x4 register blocking ----
    // IN_Y rows * 8 groups of 4 outputs = 400 items.
    #pragma unroll
    for (int it = 0; it < 2; it++) {
        const int wi = tid + it * 256;
        if (wi < IN_Y * 8) {
            const int r  = wi >> 3;
            const int x0 = (wi & 7) * 4;
            u64 uv[14], sq[14];
            #pragma unroll
            for (int k = 0; k < 14; k++) {
                uv[k] = s_uv[r][x0 + k];
                sq[k] = f2mul(uv[k], uv[k]);
            }
            #pragma unroll
            for (int o = 0; o < 4; o++) {
                u64 a1 = 0ull, a2 = 0ull;
                #pragma unroll
                for (int j = 0; j < WS; j++) {
                    a1 = f2fma(ggr[j], uv[o + j], a1);   // (P, M)
                    a2 = f2fma(ggr[j], sq[o + j], a2);   // (S, D)
                }
                s_pm[r][x0 + o] = a1;
                s_sd[r][x0 + o] = a2;
            }
        }
    }
    __syncthreads();

    // ---- Phase 2: vertical pass, x5 register blocking, two sweeps ----
    // 32 cols * 8 y-groups of 5 rows = 256 items: one per thread.
    const int x  = tid & 31;
    const int y0 = (tid >> 5) * 5;

    u64 ggc[WS];
    #pragma unroll
    for (int i = 0; i < WS; i++) ggc[i] = pk2(gcf[i], gcf[i]);

    u64 t[15];
    // Sweep A: (P, M)
    #pragma unroll
    for (int k = 0; k < 15; k++) t[k] = s_pm[y0 + k][x];
    u64 pm[5];
    #pragma unroll
    for (int o = 0; o < 5; o++) {
        u64 acc_pm = 0ull;
        #pragma unroll
        for (int i = 0; i < WS; i++) acc_pm = f2fma(ggc[i], t[o + i], acc_pm);
        pm[o] = acc_pm;
    }
    // Sweep B: (S, D) + epilogue
    #pragma unroll
    for (int k = 0; k < 15; k++) t[k] = s_sd[y0 + k][x];

    double acc = 0.0;
    const bool xok = (ox + x) < OUT_W;
    #pragma unroll
    for (int o = 0; o < 5; o++) {
        u64 acc_sd = 0ull;
        #pragma unroll
        for (int i = 0; i < WS; i++) acc_sd = f2fma(ggc[i], t[o + i], acc_sd);
        float P, M, S, D;
        upk2(P, M, pm[o]);
        upk2(S, D, acc_sd);
        const float p2  = P * P;
        const float m2  = M * M;
        const float dd  = p2 - m2;          // 4*mu12
        const float aa  = p2 + m2;          // 2*(mu1^2+mu2^2)
        const float num = dd * ((S - D) - dd);
        const float den = aa * ((S + D) - aa);
        if (xok && (oy + y0 + o) < OUT_W)
            acc += (double)__fdividef(num, den);
    }

    // ---- Deterministic block reduction ----
    #pragma unroll
    for (int off = 16; off > 0; off >>= 1)
        acc += __shfl_down_sync(0xffffffffu, acc, off);
    if ((tid & 31) == 0) s_red[tid >> 5] = acc;
    __syncthreads();

    const int bidx = (z * NTY + (int)blockIdx.y) * NTX + (int)blockIdx.x;
    __shared__ bool s_last;
    if (tid == 0) {
        double v = s_red[0] + s_red[1] + s_red[2] + s_red[3]
                 + s_red[4] + s_red[5] + s_red[6] + s_red[7];
        g_partials[bidx] = v;
        __threadfence();
        const unsigned prev = atomicAdd(&g_count, 1u);
        s_last = (prev == (unsigned)(NBLOCKS - 1));
    }
    __syncthreads();

    // ---- Last block: deterministic final reduction ----
    if (s_last) {
        __threadfence();
        double r = 0.0;
        for (int i = tid; i < NBLOCKS; i += 256)
            r += g_partials[i];
        #pragma unroll
        for (int off = 16; off > 0; off >>= 1)
            r += __shfl_down_sync(0xffffffffu, r, off);
        if ((tid & 31) == 0) s_red[tid >> 5] = r;
        __syncthreads();
        if (tid == 0) {
            double v = s_red[0] + s_red[1] + s_red[2] + s_red[3]
                     + s_red[4] + s_red[5] + s_red[6] + s_red[7];
            const double total = (double)NIMG * (double)OUT_W * (double)OUT_W;
            out[0] = (float)(v / total);
            g_count = 0;   // reset for next graph replay
        }
    }
}

extern "C" void kernel_launch(void* const* d_in, const int* in_sizes, int n_in,
                              void* d_out, int out_size)
{
    (void)in_sizes; (void)n_in; (void)out_size;
    const float* img1 = (const float*)d_in[0];
    const float* img2 = (const float*)d_in[1];
    const float* win  = (const float*)d_in[2];
    float* out = (float*)d_out;

    dim3 grid(NTX, NTY, NIMG);
    ssim_kernel<<<grid, 256>>>(img1, img2, win, out);
}

// round 6
// speedup vs baseline: 1.3432x; 1.3432x over previous
#include <cuda_runtime.h>

// SSIM fused, (16,3,512,512) fp32, separable 11x11 Gaussian, VALID -> 502x502, mean.
// Column-streaming: one 512-thread block per (image, row-strip). Each thread owns
// one column. Per input row: stage packed (u,v)=(a+b,a-b) row in smem (double
// buffered), horizontal conv from smem, vertical conv via an 11-slot register
// ring with compile-time phase rotation. No x-halo, no intermediate smem arrays.
// u=a+b, v=a-b; P=conv(u), M=conv(v), S=conv(u^2), D=conv(v^2)
// ssim = (P^2-M^2)(S-D-(P^2-M^2)) / ((P^2+M^2)(S+D-(P^2+M^2)))

#define WS      11
#define IMG_W   512
#define OUT_W   502
#define R_OUT   84
#define NSTRIP  6                   // 6*84 = 504 >= 502
#define NIMG    48
#define NBLOCKS (NIMG * NSTRIP)     // 288
#define NTHR    512

typedef unsigned long long u64;

__device__ double g_partials[NBLOCKS];
__device__ unsigned int g_count = 0;

__device__ __forceinline__ u64 pk2(float lo, float hi) {
    u64 r; asm("mov.b64 %0,{%1,%2};" : "=l"(r) : "f"(lo), "f"(hi)); return r;
}
__device__ __forceinline__ void upk2(float& lo, float& hi, u64 a) {
    asm("mov.b64 {%0,%1},%2;" : "=f"(lo), "=f"(hi) : "l"(a));
}
__device__ __forceinline__ u64 f2fma(u64 a, u64 b, u64 c) {
    u64 d; asm("fma.rn.f32x2 %0,%1,%2,%3;" : "=l"(d) : "l"(a), "l"(b), "l"(c)); return d;
}
__device__ __forceinline__ u64 f2mul(u64 a, u64 b) {
    u64 d; asm("mul.rn.f32x2 %0,%1,%2;" : "=l"(d) : "l"(a), "l"(b)); return d;
}

__global__ __launch_bounds__(NTHR, 1)
void ssim_kernel(const float* __restrict__ img1,
                 const float* __restrict__ img2,
                 const float* __restrict__ win,
                 float* __restrict__ out)
{
    __shared__ u64    s_row[2][IMG_W];   // packed (u,v), double buffered: 8 KB
    __shared__ double s_red[16];
    __shared__ bool   s_last;

    const int x     = threadIdx.x;       // column, 0..511
    const int strip = blockIdx.x;        // 0..5
    const int z     = blockIdx.y;        // 0..47
    const int c     = z % 3;
    const int y0    = strip * R_OUT;
    const int yin_end = min(y0 + R_OUT + WS - 1, IMG_W);  // exclusive input row bound
    const bool xok  = (x < OUT_W);

    // 1D separable factors from the outer-product window.
    const float* w = win + c * WS * WS;
    const float inv_mid = 1.0f / w[5 * WS + 5];
    u64 gr2[WS], gc2[WS];
    #pragma unroll
    for (int j = 0; j < WS; j++) {
        const float gr = w[5 * WS + j];
        const float gc = w[j * WS + 5] * inv_mid;
        gr2[j] = pk2(gr, gr);
        gc2[j] = pk2(gc, gc);
    }

    const float* b1 = img1 + (size_t)z * IMG_W * IMG_W;
    const float* b2 = img2 + (size_t)z * IMG_W * IMG_W;

    // Vertical ring accumulators: slot s holds pending output with (y_out-y0) % 11 == s.
    u64 apm[WS], asd[WS];
    #pragma unroll
    for (int k = 0; k < WS; k++) { apm[k] = 0ull; asd[k] = 0ull; }

    double acc = 0.0;

    // Prologue: stage row y0 into buf0; preload row y0+1 into regs.
    float a1A, a2A;
    {
        const float u1 = b1[(size_t)y0 * IMG_W + x];
        const float u2 = b2[(size_t)y0 * IMG_W + x];
        s_row[0][x] = pk2(u1 + u2, u1 - u2);
        a1A = b1[(size_t)(y0 + 1) * IMG_W + x];
        a2A = b2[(size_t)(y0 + 1) * IMG_W + x];
    }
    __syncthreads();

    // ---- Warmup: rows d = 0..10 (phase p == d), compile-time ring guards ----
    #pragma unroll
    for (int p = 0; p <= 10; p++) {
        const int y  = y0 + p;
        const int yn = y + 2;
        float a1B = 0.f, a2B = 0.f;
        if (yn < yin_end) {
            a1B = b1[(size_t)yn * IMG_W + x];
            a2B = b2[(size_t)yn * IMG_W + x];
        }
        if (xok) {
            const u64* rowp = s_row[p & 1];
            u64 Hpm = 0ull, Hsd = 0ull;
            #pragma unroll
            for (int j = 0; j < WS; j++) {
                const u64 uv = rowp[x + j];
                Hpm = f2fma(gr2[j], uv, Hpm);
                Hsd = f2fma(gr2[j], f2mul(uv, uv), Hsd);
            }
            #pragma unroll
            for (int k = 0; k < WS; k++) {
                if (k <= p) {                      // compile-time: y_out >= y0 only
                    const int s = p - k;
                    apm[s] = f2fma(gc2[k], Hpm, apm[s]);
                    asd[s] = f2fma(gc2[k], Hsd, asd[s]);
                }
            }
            if (p == 10) {                         // first completed output: y0, slot 0
                float P, M, S, D;
                upk2(P, M, apm[0]);
                upk2(S, D, asd[0]);
                const float p2 = P * P, m2 = M * M;
                const float dd = p2 - m2, aa = p2 + m2;
                acc += (double)__fdividef(dd * ((S - D) - dd), aa * ((S + D) - aa));
                apm[0] = 0ull; asd[0] = 0ull;
            }
        }
        if (y + 1 < yin_end)
            s_row[(p + 1) & 1][x] = pk2(a1A + a2A, a1A - a2A);
        a1A = a1B; a2A = a2B;
        __syncthreads();
    }

    // ---- Steady state: d = 11 .. dmax-1, unrolled by 11 for free ring rotation ----
    const int dmax = yin_end - y0;   // 94 (strips 0-4) or 92 (strip 5)
    for (int dbase = 11; dbase < dmax; dbase += 11) {
        #pragma unroll
        for (int p = 0; p < 11; p++) {
            const int d = dbase + p;
            if (d < dmax) {
                const int y  = y0 + d;
                const int yn = y + 2;
                float a1B = 0.f, a2B = 0.f;
                if (yn < yin_end) {
                    a1B = b1[(size_t)yn * IMG_W + x];
                    a2B = b2[(size_t)yn * IMG_W + x];
                }
                if (xok) {
                    const u64* rowp = s_row[d & 1];
                    u64 Hpm = 0ull, Hsd = 0ull;
                    #pragma unroll
                    for (int j = 0; j < WS; j++) {
                        const u64 uv = rowp[x + j];
                        Hpm = f2fma(gr2[j], uv, Hpm);
                        Hsd = f2fma(gr2[j], f2mul(uv, uv), Hsd);
                    }
                    #pragma unroll
                    for (int k = 0; k < WS; k++) {
                        const int s = (p - k + 11) % 11;   // compile-time
                        apm[s] = f2fma(gc2[k], Hpm, apm[s]);
                        asd[s] = f2fma(gc2[k], Hsd, asd[s]);
                    }
                    // Emit completed output y_out = y-10, slot (p+1)%11.
                    // Bounds: yin_end clamp guarantees y_out < min(y0+R_OUT, 502).
                    const int se = (p + 1) % 11;
                    float P, M, S, D;
                    upk2(P, M, apm[se]);
                    upk2(S, D, asd[se]);
                    const float p2 = P * P, m2 = M * M;
                    const float dd = p2 - m2, aa = p2 + m2;
                    acc += (double)__fdividef(dd * ((S - D) - dd), aa * ((S + D) - aa));
                    apm[se] = 0ull; asd[se] = 0ull;
                }
                if (y + 1 < yin_end)
                    s_row[(d + 1) & 1][x] = pk2(a1A + a2A, a1A - a2A);
                a1A = a1B; a2A = a2B;
                __syncthreads();
            }
        }
    }

    // ---- Deterministic block reduction (16 warps) ----
    #pragma unroll
    for (int off = 16; off > 0; off >>= 1)
        acc += __shfl_down_sync(0xffffffffu, acc, off);
    if ((x & 31) == 0) s_red[x >> 5] = acc;
    __syncthreads();

    const int bidx = z * NSTRIP + strip;
    if (x == 0) {
        double v = 0.0;
        #pragma unroll
        for (int i = 0; i < 16; i++) v += s_red[i];
        g_partials[bidx] = v;
        __threadfence();
        const unsigned prev = atomicAdd(&g_count, 1u);
        s_last = (prev == (unsigned)(NBLOCKS - 1));
    }
    __syncthreads();

    // ---- Last block: deterministic final reduction over 288 partials ----
    if (s_last) {
        __threadfence();
        double r = (x < NBLOCKS) ? g_partials[x] : 0.0;
        #pragma unroll
        for (int off = 16; off > 0; off >>= 1)
            r += __shfl_down_sync(0xffffffffu, r, off);
        if ((x & 31) == 0) s_red[x >> 5] = r;
        __syncthreads();
        if (x == 0) {
            double v = 0.0;
            #pragma unroll
            for (int i = 0; i < 16; i++) v += s_red[i];
            const double total = (double)NIMG * (double)OUT_W * (double)OUT_W;
            out[0] = (float)(v / total);
            g_count = 0;   // reset for next graph replay
        }
    }
}

extern "C" void kernel_launch(void* const* d_in, const int* in_sizes, int n_in,
                              void* d_out, int out_size)
{
    (void)in_sizes; (void)n_in; (void)out_size;
    const float* img1 = (const float*)d_in[0];
    const float* img2 = (const float*)d_in[1];
    const float* win  = (const float*)d_in[2];
    float* out = (float*)d_out;

    dim3 grid(NSTRIP, NIMG, 1);
    ssim_kernel<<<grid, NTHR>>>(img1, img2, win, out);
}